// round 8
// baseline (speedup 1.0000x reference)
#include <cuda_runtime.h>
#include <cstdint>

#define THRESH 1.25f

constexpr int B    = 16;
constexpr int CIN  = 8192;   // 64*64*2
constexpr int CHID = 512;
constexpr int COUT = 100;
constexpr int T    = 300;
constexpr int NW0  = CIN / 32;   // 256 words per (b,t)
constexpr int NW1  = CHID / 32;  // 16 words per (b,t)
constexpr int HW   = NW0 / 2;    // 128 words per half

// ---------------- scratch (static device globals; allocation-free) -------------
__device__ __align__(256) float    d_WT1[CIN * CHID];     // 16 MB  [i][o]
__device__ __align__(256) float    d_WT2[CHID * CHID];    // 1 MB   [i][o]
__device__ __align__(256) float    d_WT3[CHID * 128];     // 256 KB [i][o pad 128]
__device__ __align__(256) float    d_scale1[CHID];
__device__ __align__(256) float    d_scale2[CHID];
__device__ __align__(256) float    d_scale3[128];
__device__ __align__(256) unsigned d_bits0[T * B * NW0];  // input spikes [t][b][w]
__device__ __align__(256) unsigned d_bits1[T * B * NW1];  // hidden spikes [t][b][w]
__device__ __align__(256) unsigned d_bits2[T * B * NW1];
__device__ __align__(256) float    d_zpart[2][T * B * CHID]; // layer-1 i-half partials
__device__ __align__(256) float    d_z [T * B * CHID];    // layer-2 z [t][b][o]
__device__ __align__(256) float    d_z3[T * B * COUT];

// ---------------- row norms: scale[o] = g[o] / ||v[o,:]|| ----------------------
template <int L>
__global__ void row_norm(const float* __restrict__ v, const float* __restrict__ g)
{
    constexpr int NI = (L == 0) ? CIN : CHID;
    float* scale = (L == 0) ? d_scale1 : (L == 1) ? d_scale2 : d_scale3;
    int r = blockIdx.x;
    const float* row = v + (size_t)r * NI;
    float s = 0.f;
    for (int i = threadIdx.x; i < NI; i += 256) { float x = row[i]; s = fmaf(x, x, s); }
    #pragma unroll
    for (int d = 16; d > 0; d >>= 1) s += __shfl_down_sync(0xffffffffu, s, d);
    __shared__ float red[8];
    int lane = threadIdx.x & 31, w = threadIdx.x >> 5;
    if (lane == 0) red[w] = s;
    __syncthreads();
    if (threadIdx.x == 0) {
        float tot = 0.f;
        #pragma unroll
        for (int j = 0; j < 8; j++) tot += red[j];
        scale[r] = g[r] / sqrtf(tot);
    }
}

// ---------------- transpose + scale: WT[i][o] = v[o][i] * scale[o] -------------
template <int L>
__global__ void wnorm_transpose(const float* __restrict__ v)
{
    constexpr int NI      = (L == 0) ? CIN : CHID;
    constexpr int OSTRIDE = (L == 2) ? 128 : CHID;
    constexpr int NOV     = (L == 2) ? COUT : CHID;
    float* wt = (L == 0) ? d_WT1 : (L == 1) ? d_WT2 : d_WT3;
    const float* scale = (L == 0) ? d_scale1 : (L == 1) ? d_scale2 : d_scale3;

    __shared__ float tile[64][65];
    int i0 = blockIdx.x * 64, o0 = blockIdx.y * 64;
    int tid = threadIdx.x;
    int oy = tid >> 4;
    int ix = (tid & 15) * 4;

    #pragma unroll
    for (int k = 0; k < 4; k++) {
        int ol = oy + k * 16;
        int o  = o0 + ol;
        float4 val = make_float4(0.f, 0.f, 0.f, 0.f);
        if (o < NOV) val = *(const float4*)&v[(size_t)o * NI + i0 + ix];
        tile[ix + 0][ol] = val.x;
        tile[ix + 1][ol] = val.y;
        tile[ix + 2][ol] = val.z;
        tile[ix + 3][ol] = val.w;
    }
    __syncthreads();

    int iy = tid >> 4;
    int ox = (tid & 15) * 4;
    float4 sc;
    sc.x = (o0 + ox + 0 < NOV) ? scale[o0 + ox + 0] : 0.f;
    sc.y = (o0 + ox + 1 < NOV) ? scale[o0 + ox + 1] : 0.f;
    sc.z = (o0 + ox + 2 < NOV) ? scale[o0 + ox + 2] : 0.f;
    sc.w = (o0 + ox + 3 < NOV) ? scale[o0 + ox + 3] : 0.f;
    #pragma unroll
    for (int k = 0; k < 4; k++) {
        int il = iy + k * 16;
        float4 w;
        w.x = tile[il][ox + 0] * sc.x;
        w.y = tile[il][ox + 1] * sc.y;
        w.z = tile[il][ox + 2] * sc.z;
        w.w = tile[il][ox + 3] * sc.w;
        *(float4*)&wt[(size_t)(i0 + il) * OSTRIDE + o0 + ox] = w;
    }
}

// ---------------- bitpack, coalesced: block = (b_local, ig) --------------------
// phase 1: 8 warps x 4 rows, lanes read consecutive float4 along t (coalesced),
//          pack 4 preds -> u32 byte-store into smem [i][t] (stride 308)
// phase 2: thread t OR-packs 32 bytes (column over i) -> bits word [t][b][ig]
__global__ __launch_bounds__(256) void bitpack_in(const float* __restrict__ spike, int b0)
{
    __shared__ unsigned char sb[32 * 308];
    int b  = b0 + blockIdx.x;
    int ig = blockIdx.y;
    int tid = threadIdx.x, lane = tid & 31, w = tid >> 5;

    #pragma unroll
    for (int k = 0; k < 4; k++) {
        int il = w + 8 * k;                       // 0..31
        const float4* row4 = (const float4*)(spike + ((size_t)b * CIN + ig * 32 + il) * T);
        #pragma unroll
        for (int j = 0; j < 3; j++) {
            int f = lane + 32 * j;                // float4 index, 75 per row
            if (f < 75) {
                float4 v = row4[f];
                unsigned p = (v.x > 0.5f ? 1u : 0u)
                           | (v.y > 0.5f ? 1u : 0u) << 8
                           | (v.z > 0.5f ? 1u : 0u) << 16
                           | (v.w > 0.5f ? 1u : 0u) << 24;
                *(unsigned*)&sb[il * 308 + 4 * f] = p;
            }
        }
    }
    __syncthreads();

    for (int t = tid; t < T; t += 256) {
        unsigned m = 0;
        #pragma unroll
        for (int i = 0; i < 32; i++) m |= (unsigned)sb[i * 308 + t] << i;
        d_bits0[(size_t)t * (B * NW0) + b * NW0 + ig] = m;
    }
}

// ---------------- layer-1 sparse gather, i-halved + b-chunked, float4 x 128 ----
__global__ __launch_bounds__(128) void gather_hid1(int b0)
{
    const float4* __restrict__ wt = (const float4*)d_WT1;
    int t = blockIdx.x, b = b0 + blockIdx.y, h = blockIdx.z;
    const unsigned* bp = d_bits0 + ((size_t)t * B + b) * NW0 + h * HW;

    __shared__ unsigned short sidx[HW * 32];
    __shared__ int wcnt[4];
    int tid = threadIdx.x, lane = tid & 31, w = tid >> 5;

    int word = w * 32 + lane;
    unsigned m = bp[word];
    int c = __popc(m);
    int x = c;
    #pragma unroll
    for (int d = 1; d < 32; d <<= 1) {
        int y = __shfl_up_sync(0xffffffffu, x, d);
        if (lane >= d) x += y;
    }
    if (lane == 31) wcnt[w] = x;
    __syncthreads();
    int base = 0;
    #pragma unroll
    for (int j = 0; j < 4; j++) if (j < w) base += wcnt[j];
    int mybase = base + x - c;
    while (m) {
        int bpos = __ffs((int)m) - 1;
        m &= m - 1;
        sidx[mybase++] = (unsigned short)(word * 32 + bpos);
    }
    __syncthreads();

    int cnt = wcnt[0] + wcnt[1] + wcnt[2] + wcnt[3];
    int rowbase = h * (CIN / 2);

    float ax = 0.f, ay = 0.f, az = 0.f, aw = 0.f;
    int k = 0;
    for (; k + 8 <= cnt; k += 8) {
        float4 r[8];
        #pragma unroll
        for (int u = 0; u < 8; u++) {
            int i = rowbase + sidx[k + u];
            r[u] = wt[(size_t)i * 128 + tid];
        }
        #pragma unroll
        for (int u = 0; u < 8; u++) { ax += r[u].x; ay += r[u].y; az += r[u].z; aw += r[u].w; }
    }
    for (; k < cnt; k++) {
        int i = rowbase + sidx[k];
        float4 r0 = wt[(size_t)i * 128 + tid];
        ax += r0.x; ay += r0.y; az += r0.z; aw += r0.w;
    }
    float4 o; o.x = ax; o.y = ay; o.z = az; o.w = aw;
    ((float4*)d_zpart[h])[((size_t)t * B + b) * 128 + tid] = o;
}

// ---------------- LIF layer 1: sums the 2 half-partials, depth-8 prefetch ------
__global__ void lif_hid1(const float* __restrict__ cds, const float* __restrict__ vds)
{
    int gid  = blockIdx.x * blockDim.x + threadIdx.x;  // b*512+o
    int lane = threadIdx.x & 31;
    float a  = 1.f - cds[0];
    float bb = 1.f - vds[0];
    float cur = 0.f, volt = 0.f;

    float2 zb[8];
    #pragma unroll
    for (int j = 0; j < 8; j++) {
        zb[j].x = d_zpart[0][(size_t)j * (B * CHID) + gid];
        zb[j].y = d_zpart[1][(size_t)j * (B * CHID) + gid];
    }

    #pragma unroll 8
    for (int t = 0; t < T; t++) {
        float2 p = zb[t & 7];
        float zt = p.x + p.y;
        int tp = t + 8;
        if (tp < T) {
            zb[t & 7].x = d_zpart[0][(size_t)tp * (B * CHID) + gid];
            zb[t & 7].y = d_zpart[1][(size_t)tp * (B * CHID) + gid];
        }
        cur  = fmaf(a, cur, zt);
        volt = fmaf(bb, volt, cur);
        bool s = volt >= THRESH;
        unsigned msk = __ballot_sync(0xffffffffu, s);
        volt = s ? 0.f : volt;
        if (lane == 0) d_bits1[(size_t)t * (B * NW1) + (gid >> 5)] = msk;
    }
}

// ---------------- layer-2 sparse gather, float4 x 128 ---------------------------
__global__ __launch_bounds__(128) void gather_hid2()
{
    const float4* __restrict__ wt = (const float4*)d_WT2;
    int t = blockIdx.x, b = blockIdx.y;
    const unsigned* bp = d_bits1 + ((size_t)t * B + b) * NW1;

    __shared__ unsigned short sidx[NW1 * 32];
    __shared__ int scount;
    int tid = threadIdx.x, lane = tid & 31;

    if (tid < 32) {
        unsigned m = (lane < NW1) ? bp[lane] : 0u;
        int c = __popc(m);
        int x = c;
        #pragma unroll
        for (int d = 1; d < 32; d <<= 1) {
            int y = __shfl_up_sync(0xffffffffu, x, d);
            if (lane >= d) x += y;
        }
        int base = x - c;
        while (m) {
            int bpos = __ffs((int)m) - 1;
            m &= m - 1;
            sidx[base++] = (unsigned short)(lane * 32 + bpos);
        }
        if (lane == 31) scount = x;
    }
    __syncthreads();

    int cnt = scount;
    float ax = 0.f, ay = 0.f, az = 0.f, aw = 0.f;
    int k = 0;
    for (; k + 8 <= cnt; k += 8) {
        float4 r[8];
        #pragma unroll
        for (int u = 0; u < 8; u++) { int i = sidx[k + u]; r[u] = wt[(size_t)i * 128 + tid]; }
        #pragma unroll
        for (int u = 0; u < 8; u++) { ax += r[u].x; ay += r[u].y; az += r[u].z; aw += r[u].w; }
    }
    for (; k < cnt; k++) {
        float4 r0 = wt[(size_t)sidx[k] * 128 + tid];
        ax += r0.x; ay += r0.y; az += r0.z; aw += r0.w;
    }
    float4 o; o.x = ax; o.y = ay; o.z = az; o.w = aw;
    ((float4*)d_z)[((size_t)t * B + b) * 128 + tid] = o;
}

// layer 3: 100 outputs (padded to 128)
__global__ void gather_out()
{
    int t = blockIdx.x, b = blockIdx.y;
    const unsigned* bp = d_bits2 + ((size_t)t * B + b) * NW1;

    __shared__ unsigned short sidx[NW1 * 32];
    __shared__ int scount;
    int tid = threadIdx.x, lane = tid & 31;

    if (tid < 32) {
        unsigned m = (lane < NW1) ? bp[lane] : 0u;
        int c = __popc(m);
        int x = c;
        #pragma unroll
        for (int d = 1; d < 32; d <<= 1) {
            int y = __shfl_up_sync(0xffffffffu, x, d);
            if (lane >= d) x += y;
        }
        int base = x - c;
        while (m) {
            int bpos = __ffs((int)m) - 1;
            m &= m - 1;
            sidx[base++] = (unsigned short)(lane * 32 + bpos);
        }
        if (lane == 31) scount = x;
    }
    __syncthreads();

    int cnt = scount;
    float acc = 0.f;
    int k = 0;
    for (; k + 8 <= cnt; k += 8) {
        float r[8];
        #pragma unroll
        for (int u = 0; u < 8; u++) { int i = sidx[k + u]; r[u] = d_WT3[i * 128 + tid]; }
        #pragma unroll
        for (int u = 0; u < 8; u++) acc += r[u];
    }
    for (; k < cnt; k++) acc += d_WT3[sidx[k] * 128 + tid];

    if (tid < COUT) d_z3[((size_t)t * B + b) * COUT + tid] = acc;
}

// ---------------- LIF layer 2 (reads d_z), depth-8 prefetch --------------------
__global__ void lif_hid2(const float* __restrict__ cds, const float* __restrict__ vds)
{
    int gid  = blockIdx.x * blockDim.x + threadIdx.x;
    int lane = threadIdx.x & 31;
    float a  = 1.f - cds[1];
    float bb = 1.f - vds[1];
    float cur = 0.f, volt = 0.f;

    float zbuf[8];
    #pragma unroll
    for (int j = 0; j < 8; j++) zbuf[j] = d_z[(size_t)j * (B * CHID) + gid];

    #pragma unroll 8
    for (int t = 0; t < T; t++) {
        float zt = zbuf[t & 7];
        int tp = t + 8;
        if (tp < T) zbuf[t & 7] = d_z[(size_t)tp * (B * CHID) + gid];
        cur  = fmaf(a, cur, zt);
        volt = fmaf(bb, volt, cur);
        bool s = volt >= THRESH;
        unsigned msk = __ballot_sync(0xffffffffu, s);
        volt = s ? 0.f : volt;
        if (lane == 0) d_bits2[(size_t)t * (B * NW1) + (gid >> 5)] = msk;
    }
}

// ---------------- LIF output layer -> d_out [b][c][t] float --------------------
__global__ void lif_out(const float* __restrict__ cds, const float* __restrict__ vds,
                        float* __restrict__ out)
{
    int gid = blockIdx.x * blockDim.x + threadIdx.x;
    if (gid >= B * COUT) return;
    int b = gid / COUT, c = gid % COUT;
    float a  = 1.f - cds[2];
    float bb = 1.f - vds[2];
    float cur = 0.f, volt = 0.f;
    float* orow = out + ((size_t)b * COUT + c) * T;

    float zbuf[8];
    #pragma unroll
    for (int j = 0; j < 8; j++) zbuf[j] = d_z3[(size_t)j * (B * COUT) + gid];

    #pragma unroll 8
    for (int t = 0; t < T; t++) {
        float zt = zbuf[t & 7];
        int tp = t + 8;
        if (tp < T) zbuf[t & 7] = d_z3[(size_t)tp * (B * COUT) + gid];
        cur  = fmaf(a, cur, zt);
        volt = fmaf(bb, volt, cur);
        bool s = volt >= THRESH;
        volt = s ? 0.f : volt;
        orow[t] = s ? 1.0f : 0.0f;
    }
}

// ---------------- streams/events (context resources, not tracked device mem) ---
struct SideStreams {
    cudaStream_t s1, s2;
    cudaEvent_t  evRoot, evBitsLo, evBitsHi, evPrep;
    SideStreams() {
        cudaStreamCreateWithFlags(&s1, cudaStreamNonBlocking);
        cudaStreamCreateWithFlags(&s2, cudaStreamNonBlocking);
        cudaEventCreateWithFlags(&evRoot,  cudaEventDisableTiming);
        cudaEventCreateWithFlags(&evBitsLo, cudaEventDisableTiming);
        cudaEventCreateWithFlags(&evBitsHi, cudaEventDisableTiming);
        cudaEventCreateWithFlags(&evPrep,  cudaEventDisableTiming);
    }
};
static SideStreams g_ss;

// ---------------- launch ---------------------------------------------------------
extern "C" void kernel_launch(void* const* d_in, const int* in_sizes, int n_in,
                              void* d_out, int out_size)
{
    const float* spike = (const float*)d_in[0];
    const float* v1 = (const float*)d_in[1];
    const float* g1 = (const float*)d_in[2];
    const float* v2 = (const float*)d_in[3];
    const float* g2 = (const float*)d_in[4];
    const float* v3 = (const float*)d_in[5];
    const float* g3 = (const float*)d_in[6];
    const float* cds = (const float*)d_in[7];
    const float* vds = (const float*)d_in[8];
    float* out = (float*)d_out;

    // fork
    cudaEventRecord(g_ss.evRoot, 0);
    cudaStreamWaitEvent(g_ss.s1, g_ss.evRoot, 0);
    cudaStreamWaitEvent(g_ss.s2, g_ss.evRoot, 0);

    // s1: bitpack low batches                                   -- idx 0
    bitpack_in<<<dim3(8, NW0), 256, 0, g_ss.s1>>>(spike, 0);
    cudaEventRecord(g_ss.evBitsLo, g_ss.s1);

    // main: layer-1 weight prep                                 -- idx 1, 2
    row_norm<0><<<CHID, 256>>>(v1, g1);
    wnorm_transpose<0><<<dim3(CIN / 64, CHID / 64), 256>>>(v1);

    // main: gather1 low batches                                 -- idx 3 (profiled)
    cudaStreamWaitEvent(0, g_ss.evBitsLo, 0);
    gather_hid1<<<dim3(T, 8, 2), 128>>>(0);

    // s1: bitpack high batches (runs concurrent with gather1-lo) -- idx 4
    bitpack_in<<<dim3(8, NW0), 256, 0, g_ss.s1>>>(spike, 8);
    cudaEventRecord(g_ss.evBitsHi, g_ss.s1);

    // main: gather1 high batches                                -- idx 5
    cudaStreamWaitEvent(0, g_ss.evBitsHi, 0);
    gather_hid1<<<dim3(T, 8, 2), 128>>>(8);

    // s2: layer-2/3 weight prep, concurrent with gather1
    row_norm<1><<<CHID, 256, 0, g_ss.s2>>>(v2, g2);
    row_norm<2><<<COUT, 256, 0, g_ss.s2>>>(v3, g3);
    wnorm_transpose<1><<<dim3(CHID / 64, CHID / 64), 256, 0, g_ss.s2>>>(v2);
    wnorm_transpose<2><<<dim3(CHID / 64, 2), 256, 0, g_ss.s2>>>(v3);
    cudaEventRecord(g_ss.evPrep, g_ss.s2);

    // main tail
    lif_hid1<<<(B * CHID) / 128, 128>>>(cds, vds);
    cudaStreamWaitEvent(0, g_ss.evPrep, 0);
    gather_hid2<<<dim3(T, B), 128>>>();
    lif_hid2<<<(B * CHID) / 128, 128>>>(cds, vds);
    gather_out<<<dim3(T, B), 128>>>();
    lif_out<<<(B * COUT + 127) / 128, 128>>>(cds, vds, out);
}

// round 9
// speedup vs baseline: 1.0481x; 1.0481x over previous
#include <cuda_runtime.h>
#include <cstdint>

#define THRESH 1.25f

constexpr int B    = 16;
constexpr int CIN  = 8192;   // 64*64*2
constexpr int CHID = 512;
constexpr int COUT = 100;
constexpr int T    = 300;
constexpr int NW0  = CIN / 32;   // 256 words per (b,t)
constexpr int NW1  = CHID / 32;  // 16 words per (b,t)
constexpr int HW   = NW0 / 2;    // 128 words per half

// ---------------- scratch (static device globals; allocation-free) -------------
__device__ __align__(256) float    d_WT1[CIN * CHID];     // 16 MB  [i][o]
__device__ __align__(256) float    d_WT2[CHID * CHID];    // 1 MB   [i][o]
__device__ __align__(256) float    d_WT3[CHID * 128];     // 256 KB [i][o pad 128]
__device__ __align__(256) float    d_scale1[CHID];
__device__ __align__(256) unsigned d_bits0[T * B * NW0];  // input spikes [t][b][w]
__device__ __align__(256) unsigned d_bits1[T * B * NW1];  // hidden spikes [t][b][w]
__device__ __align__(256) unsigned d_bits2[T * B * NW1];
__device__ __align__(256) float    d_zpart[2][T * B * CHID]; // layer-1 i-half partials
__device__ __align__(256) float    d_z [T * B * CHID];    // layer-2 z [t][b][o]
__device__ __align__(256) float    d_z3[T * B * COUT];

// ---------------- fused: bitpack (blocks 0..4095) + layer-1 row norms ----------
// bitpack: block=(b,ig): coalesced reads along t, smem byte-transpose, OR-pack
// norm:    blocks 4096..4607, identical reduction order to the old row_norm<0>
__global__ __launch_bounds__(256) void bitpack_norm0(const float* __restrict__ spike,
                                                     const float* __restrict__ v1,
                                                     const float* __restrict__ g1)
{
    __shared__ unsigned char sb[32 * 308];
    __shared__ float red[8];
    int blk = blockIdx.x;
    int tid = threadIdx.x, lane = tid & 31, w = tid >> 5;

    if (blk < 4096) {
        int b  = blk >> 8;
        int ig = blk & 255;
        #pragma unroll
        for (int k = 0; k < 4; k++) {
            int il = w + 8 * k;
            const float4* row4 = (const float4*)(spike + ((size_t)b * CIN + ig * 32 + il) * T);
            #pragma unroll
            for (int j = 0; j < 3; j++) {
                int f = lane + 32 * j;
                if (f < 75) {
                    float4 v = row4[f];
                    unsigned p = (v.x > 0.5f ? 1u : 0u)
                               | (v.y > 0.5f ? 1u : 0u) << 8
                               | (v.z > 0.5f ? 1u : 0u) << 16
                               | (v.w > 0.5f ? 1u : 0u) << 24;
                    *(unsigned*)&sb[il * 308 + 4 * f] = p;
                }
            }
        }
        __syncthreads();
        for (int t = tid; t < T; t += 256) {
            unsigned m = 0;
            #pragma unroll
            for (int i = 0; i < 32; i++) m |= (unsigned)sb[i * 308 + t] << i;
            d_bits0[(size_t)t * (B * NW0) + b * NW0 + ig] = m;
        }
    } else {
        int r = blk - 4096;   // 0..511
        const float* row = v1 + (size_t)r * CIN;
        float s = 0.f;
        for (int i = tid; i < CIN; i += 256) { float x = row[i]; s = fmaf(x, x, s); }
        #pragma unroll
        for (int d = 16; d > 0; d >>= 1) s += __shfl_down_sync(0xffffffffu, s, d);
        if (lane == 0) red[w] = s;
        __syncthreads();
        if (tid == 0) {
            float tot = 0.f;
            #pragma unroll
            for (int j = 0; j < 8; j++) tot += red[j];
            d_scale1[r] = g1[r] / sqrtf(tot);
        }
    }
}

// ---------------- layer-1 transpose + scale: WT1[i][o] = v1[o][i]*scale1[o] ----
__global__ void wnorm_t0(const float* __restrict__ v)
{
    __shared__ float tile[64][65];
    int i0 = blockIdx.x * 64, o0 = blockIdx.y * 64;
    int tid = threadIdx.x;
    int oy = tid >> 4;
    int ix = (tid & 15) * 4;

    #pragma unroll
    for (int k = 0; k < 4; k++) {
        int ol = oy + k * 16;
        float4 val = *(const float4*)&v[(size_t)(o0 + ol) * CIN + i0 + ix];
        tile[ix + 0][ol] = val.x;
        tile[ix + 1][ol] = val.y;
        tile[ix + 2][ol] = val.z;
        tile[ix + 3][ol] = val.w;
    }
    __syncthreads();

    int iy = tid >> 4;
    int ox = (tid & 15) * 4;
    float4 sc = *(const float4*)&d_scale1[o0 + ox];
    #pragma unroll
    for (int k = 0; k < 4; k++) {
        int il = iy + k * 16;
        float4 w;
        w.x = tile[il][ox + 0] * sc.x;
        w.y = tile[il][ox + 1] * sc.y;
        w.z = tile[il][ox + 2] * sc.z;
        w.w = tile[il][ox + 3] * sc.w;
        *(float4*)&d_WT1[(size_t)(i0 + il) * CHID + o0 + ox] = w;
    }
}

// ---------------- fused prep for layers 2+3: norms (recomputed/block) + transp --
// blocks 0..63: layer2 (8x8 tiles of 64x64); blocks 64..79: layer3 (8x2 tiles)
__global__ __launch_bounds__(256) void fused_prep23(const float* __restrict__ v2,
                                                    const float* __restrict__ g2,
                                                    const float* __restrict__ v3,
                                                    const float* __restrict__ g3)
{
    int blk = blockIdx.x;
    const float *v, *g;
    float* wt;
    int bx, by, OSTRIDE, NOV;
    if (blk < 64) { v = v2; g = g2; wt = d_WT2; bx = blk & 7; by = blk >> 3; OSTRIDE = 512; NOV = 512; }
    else { int l = blk - 64; v = v3; g = g3; wt = d_WT3; bx = l & 7; by = l >> 3; OSTRIDE = 128; NOV = 100; }
    constexpr int NI = 512;
    int i0 = bx * 64, o0 = by * 64;

    __shared__ float sscale[64];
    __shared__ float tile[64][65];
    int tid = threadIdx.x, lane = tid & 31, w = tid >> 5;

    // norms: warp w computes rows o0 + w*8 .. +7 (full 512-elem row each)
    #pragma unroll
    for (int r = 0; r < 8; r++) {
        int o = o0 + w * 8 + r;
        float s = 0.f;
        if (o < NOV) {
            const float* row = v + (size_t)o * NI;
            #pragma unroll
            for (int k = 0; k < 16; k++) { float x = row[lane + 32 * k]; s = fmaf(x, x, s); }
        }
        #pragma unroll
        for (int d = 16; d > 0; d >>= 1) s += __shfl_down_sync(0xffffffffu, s, d);
        if (lane == 0) sscale[w * 8 + r] = (o < NOV) ? g[o] / sqrtf(s) : 0.f;
    }
    __syncthreads();

    int oy = tid >> 4;
    int ix = (tid & 15) * 4;
    #pragma unroll
    for (int k = 0; k < 4; k++) {
        int ol = oy + k * 16;
        int o  = o0 + ol;
        float4 val = make_float4(0.f, 0.f, 0.f, 0.f);
        if (o < NOV) val = *(const float4*)&v[(size_t)o * NI + i0 + ix];
        tile[ix + 0][ol] = val.x;
        tile[ix + 1][ol] = val.y;
        tile[ix + 2][ol] = val.z;
        tile[ix + 3][ol] = val.w;
    }
    __syncthreads();

    int iy = tid >> 4;
    int ox = (tid & 15) * 4;
    float4 sc;
    sc.x = sscale[ox + 0]; sc.y = sscale[ox + 1];
    sc.z = sscale[ox + 2]; sc.w = sscale[ox + 3];
    #pragma unroll
    for (int k = 0; k < 4; k++) {
        int il = iy + k * 16;
        float4 w4;
        w4.x = tile[il][ox + 0] * sc.x;
        w4.y = tile[il][ox + 1] * sc.y;
        w4.z = tile[il][ox + 2] * sc.z;
        w4.w = tile[il][ox + 3] * sc.w;
        *(float4*)&wt[(size_t)(i0 + il) * OSTRIDE + o0 + ox] = w4;
    }
}

// ---------------- layer-1 sparse gather, i-halved, float4 x 128, full B --------
__global__ __launch_bounds__(128) void gather_hid1()
{
    const float4* __restrict__ wt = (const float4*)d_WT1;
    int t = blockIdx.x, b = blockIdx.y, h = blockIdx.z;
    const unsigned* bp = d_bits0 + ((size_t)t * B + b) * NW0 + h * HW;

    __shared__ unsigned short sidx[HW * 32];
    __shared__ int wcnt[4];
    int tid = threadIdx.x, lane = tid & 31, w = tid >> 5;

    int word = w * 32 + lane;
    unsigned m = bp[word];
    int c = __popc(m);
    int x = c;
    #pragma unroll
    for (int d = 1; d < 32; d <<= 1) {
        int y = __shfl_up_sync(0xffffffffu, x, d);
        if (lane >= d) x += y;
    }
    if (lane == 31) wcnt[w] = x;
    __syncthreads();
    int base = 0;
    #pragma unroll
    for (int j = 0; j < 4; j++) if (j < w) base += wcnt[j];
    int mybase = base + x - c;
    while (m) {
        int bpos = __ffs((int)m) - 1;
        m &= m - 1;
        sidx[mybase++] = (unsigned short)(word * 32 + bpos);
    }
    __syncthreads();

    int cnt = wcnt[0] + wcnt[1] + wcnt[2] + wcnt[3];
    int rowbase = h * (CIN / 2);

    float ax = 0.f, ay = 0.f, az = 0.f, aw = 0.f;
    int k = 0;
    for (; k + 8 <= cnt; k += 8) {
        float4 r[8];
        #pragma unroll
        for (int u = 0; u < 8; u++) {
            int i = rowbase + sidx[k + u];
            r[u] = wt[(size_t)i * 128 + tid];
        }
        #pragma unroll
        for (int u = 0; u < 8; u++) { ax += r[u].x; ay += r[u].y; az += r[u].z; aw += r[u].w; }
    }
    for (; k < cnt; k++) {
        int i = rowbase + sidx[k];
        float4 r0 = wt[(size_t)i * 128 + tid];
        ax += r0.x; ay += r0.y; az += r0.z; aw += r0.w;
    }
    float4 o; o.x = ax; o.y = ay; o.z = az; o.w = aw;
    ((float4*)d_zpart[h])[((size_t)t * B + b) * 128 + tid] = o;
}

// ---------------- LIF layer 1: sums the 2 half-partials, depth-8 prefetch ------
__global__ void lif_hid1(const float* __restrict__ cds, const float* __restrict__ vds)
{
    int gid  = blockIdx.x * blockDim.x + threadIdx.x;  // b*512+o
    int lane = threadIdx.x & 31;
    float a  = 1.f - cds[0];
    float bb = 1.f - vds[0];
    float cur = 0.f, volt = 0.f;

    float2 zb[8];
    #pragma unroll
    for (int j = 0; j < 8; j++) {
        zb[j].x = d_zpart[0][(size_t)j * (B * CHID) + gid];
        zb[j].y = d_zpart[1][(size_t)j * (B * CHID) + gid];
    }

    #pragma unroll 8
    for (int t = 0; t < T; t++) {
        float2 p = zb[t & 7];
        float zt = p.x + p.y;
        int tp = t + 8;
        if (tp < T) {
            zb[t & 7].x = d_zpart[0][(size_t)tp * (B * CHID) + gid];
            zb[t & 7].y = d_zpart[1][(size_t)tp * (B * CHID) + gid];
        }
        cur  = fmaf(a, cur, zt);
        volt = fmaf(bb, volt, cur);
        bool s = volt >= THRESH;
        unsigned msk = __ballot_sync(0xffffffffu, s);
        volt = s ? 0.f : volt;
        if (lane == 0) d_bits1[(size_t)t * (B * NW1) + (gid >> 5)] = msk;
    }
}

// ---------------- layer-2 sparse gather, float4 x 128 ---------------------------
__global__ __launch_bounds__(128) void gather_hid2()
{
    const float4* __restrict__ wt = (const float4*)d_WT2;
    int t = blockIdx.x, b = blockIdx.y;
    const unsigned* bp = d_bits1 + ((size_t)t * B + b) * NW1;

    __shared__ unsigned short sidx[NW1 * 32];
    __shared__ int scount;
    int tid = threadIdx.x, lane = tid & 31;

    if (tid < 32) {
        unsigned m = (lane < NW1) ? bp[lane] : 0u;
        int c = __popc(m);
        int x = c;
        #pragma unroll
        for (int d = 1; d < 32; d <<= 1) {
            int y = __shfl_up_sync(0xffffffffu, x, d);
            if (lane >= d) x += y;
        }
        int base = x - c;
        while (m) {
            int bpos = __ffs((int)m) - 1;
            m &= m - 1;
            sidx[base++] = (unsigned short)(lane * 32 + bpos);
        }
        if (lane == 31) scount = x;
    }
    __syncthreads();

    int cnt = scount;
    float ax = 0.f, ay = 0.f, az = 0.f, aw = 0.f;
    int k = 0;
    for (; k + 8 <= cnt; k += 8) {
        float4 r[8];
        #pragma unroll
        for (int u = 0; u < 8; u++) { int i = sidx[k + u]; r[u] = wt[(size_t)i * 128 + tid]; }
        #pragma unroll
        for (int u = 0; u < 8; u++) { ax += r[u].x; ay += r[u].y; az += r[u].z; aw += r[u].w; }
    }
    for (; k < cnt; k++) {
        float4 r0 = wt[(size_t)sidx[k] * 128 + tid];
        ax += r0.x; ay += r0.y; az += r0.z; aw += r0.w;
    }
    float4 o; o.x = ax; o.y = ay; o.z = az; o.w = aw;
    ((float4*)d_z)[((size_t)t * B + b) * 128 + tid] = o;
}

// layer 3: 100 outputs (padded to 128)
__global__ void gather_out()
{
    int t = blockIdx.x, b = blockIdx.y;
    const unsigned* bp = d_bits2 + ((size_t)t * B + b) * NW1;

    __shared__ unsigned short sidx[NW1 * 32];
    __shared__ int scount;
    int tid = threadIdx.x, lane = tid & 31;

    if (tid < 32) {
        unsigned m = (lane < NW1) ? bp[lane] : 0u;
        int c = __popc(m);
        int x = c;
        #pragma unroll
        for (int d = 1; d < 32; d <<= 1) {
            int y = __shfl_up_sync(0xffffffffu, x, d);
            if (lane >= d) x += y;
        }
        int base = x - c;
        while (m) {
            int bpos = __ffs((int)m) - 1;
            m &= m - 1;
            sidx[base++] = (unsigned short)(lane * 32 + bpos);
        }
        if (lane == 31) scount = x;
    }
    __syncthreads();

    int cnt = scount;
    float acc = 0.f;
    int k = 0;
    for (; k + 8 <= cnt; k += 8) {
        float r[8];
        #pragma unroll
        for (int u = 0; u < 8; u++) { int i = sidx[k + u]; r[u] = d_WT3[i * 128 + tid]; }
        #pragma unroll
        for (int u = 0; u < 8; u++) acc += r[u];
    }
    for (; k < cnt; k++) acc += d_WT3[sidx[k] * 128 + tid];

    if (tid < COUT) d_z3[((size_t)t * B + b) * COUT + tid] = acc;
}

// ---------------- LIF layer 2 (reads d_z), depth-8 prefetch --------------------
__global__ void lif_hid2(const float* __restrict__ cds, const float* __restrict__ vds)
{
    int gid  = blockIdx.x * blockDim.x + threadIdx.x;
    int lane = threadIdx.x & 31;
    float a  = 1.f - cds[1];
    float bb = 1.f - vds[1];
    float cur = 0.f, volt = 0.f;

    float zbuf[8];
    #pragma unroll
    for (int j = 0; j < 8; j++) zbuf[j] = d_z[(size_t)j * (B * CHID) + gid];

    #pragma unroll 8
    for (int t = 0; t < T; t++) {
        float zt = zbuf[t & 7];
        int tp = t + 8;
        if (tp < T) zbuf[t & 7] = d_z[(size_t)tp * (B * CHID) + gid];
        cur  = fmaf(a, cur, zt);
        volt = fmaf(bb, volt, cur);
        bool s = volt >= THRESH;
        unsigned msk = __ballot_sync(0xffffffffu, s);
        volt = s ? 0.f : volt;
        if (lane == 0) d_bits2[(size_t)t * (B * NW1) + (gid >> 5)] = msk;
    }
}

// ---------------- LIF output layer -> d_out [b][c][t] float --------------------
__global__ void lif_out(const float* __restrict__ cds, const float* __restrict__ vds,
                        float* __restrict__ out)
{
    int gid = blockIdx.x * blockDim.x + threadIdx.x;
    if (gid >= B * COUT) return;
    int b = gid / COUT, c = gid % COUT;
    float a  = 1.f - cds[2];
    float bb = 1.f - vds[2];
    float cur = 0.f, volt = 0.f;
    float* orow = out + ((size_t)b * COUT + c) * T;

    float zbuf[8];
    #pragma unroll
    for (int j = 0; j < 8; j++) zbuf[j] = d_z3[(size_t)j * (B * COUT) + gid];

    #pragma unroll 8
    for (int t = 0; t < T; t++) {
        float zt = zbuf[t & 7];
        int tp = t + 8;
        if (tp < T) zbuf[t & 7] = d_z3[(size_t)tp * (B * COUT) + gid];
        cur  = fmaf(a, cur, zt);
        volt = fmaf(bb, volt, cur);
        bool s = volt >= THRESH;
        volt = s ? 0.f : volt;
        orow[t] = s ? 1.0f : 0.0f;
    }
}

// ---------------- streams/events (context resources, not tracked device mem) ---
struct SideStreams {
    cudaStream_t s1, s2;
    cudaEvent_t  evRoot, evBits, evPrep;
    SideStreams() {
        cudaStreamCreateWithFlags(&s1, cudaStreamNonBlocking);
        cudaStreamCreateWithFlags(&s2, cudaStreamNonBlocking);
        cudaEventCreateWithFlags(&evRoot, cudaEventDisableTiming);
        cudaEventCreateWithFlags(&evBits, cudaEventDisableTiming);
        cudaEventCreateWithFlags(&evPrep, cudaEventDisableTiming);
    }
};
static SideStreams g_ss;

// ---------------- launch ---------------------------------------------------------
extern "C" void kernel_launch(void* const* d_in, const int* in_sizes, int n_in,
                              void* d_out, int out_size)
{
    const float* spike = (const float*)d_in[0];
    const float* v1 = (const float*)d_in[1];
    const float* g1 = (const float*)d_in[2];
    const float* v2 = (const float*)d_in[3];
    const float* g2 = (const float*)d_in[4];
    const float* v3 = (const float*)d_in[5];
    const float* g3 = (const float*)d_in[6];
    const float* cds = (const float*)d_in[7];
    const float* vds = (const float*)d_in[8];
    float* out = (float*)d_out;

    // fork
    cudaEventRecord(g_ss.evRoot, 0);
    cudaStreamWaitEvent(g_ss.s1, g_ss.evRoot, 0);
    cudaStreamWaitEvent(g_ss.s2, g_ss.evRoot, 0);

    // #1: layers 2+3 full weight prep (s2)
    fused_prep23<<<80, 256, 0, g_ss.s2>>>(v2, g2, v3, g3);
    cudaEventRecord(g_ss.evPrep, g_ss.s2);

    // #2: bitpack + layer-1 norms (s1)
    bitpack_norm0<<<4096 + CHID, 256, 0, g_ss.s1>>>(spike, v1, g1);
    cudaEventRecord(g_ss.evBits, g_ss.s1);

    // main chain
    cudaStreamWaitEvent(0, g_ss.evBits, 0);
    wnorm_t0<<<dim3(CIN / 64, CHID / 64), 256>>>(v1);        // #3
    gather_hid1<<<dim3(T, B, 2), 128>>>();                   // #4
    lif_hid1<<<(B * CHID) / 128, 128>>>(cds, vds);           // #5
    cudaStreamWaitEvent(0, g_ss.evPrep, 0);
    gather_hid2<<<dim3(T, B), 128>>>();                      // #6 (profiled)
    lif_hid2<<<(B * CHID) / 128, 128>>>(cds, vds);
    gather_out<<<dim3(T, B), 128>>>();
    lif_out<<<(B * COUT + 127) / 128, 128>>>(cds, vds, out);
}